// round 4
// baseline (speedup 1.0000x reference)
#include <cuda_runtime.h>

#define N_NODES  100000
#define N_EDGES  1600000
#define HIDDEN   64
#define EMB      2
#define N_GRAPHS 64
#define NQ       (N_EDGES / 4)       // 400000 int4-quads

// -------- scratch (device globals; zero-initialized at load) --------
__device__ float    g_deg[N_NODES];      // deg accumulator (self-zeroing each call)
__device__ float2   g_nd[N_NODES];       // {dinv[n], bitcast(batch[n])}
__device__ float    g_xd[N_NODES];       // x[n]*dinv[n]
__device__ float    g_t[N_NODES];        // layer-1 unscaled agg (seeded = xd)
__device__ float2   g_hhd[N_NODES];      // hh[n]*dinv[n]
__device__ double   g_sum, g_sumsq;
__device__ float    g_pool[N_GRAPHS * 2];  // accumulated by k_hh + k_agg2 (self-zeroing)
__device__ float    g_cnt[N_GRAPHS];
__device__ unsigned g_done;

// K1: deg[d] += w   (4 edges/thread)
__global__ void k_deg(const int4* __restrict__ dst4, const float4* __restrict__ ew4) {
    int i = blockIdx.x * blockDim.x + threadIdx.x;
    if (i >= NQ) return;
    int4   d = __ldg(&dst4[i]);
    float4 w = __ldg(&ew4[i]);
    atomicAdd(&g_deg[d.x], w.x); atomicAdd(&g_deg[d.y], w.y);
    atomicAdd(&g_deg[d.z], w.z); atomicAdd(&g_deg[d.w], w.w);
}

// K2: dinv = rsqrt(deg+1); pack {dinv,batch}; xd = x*dinv; seed t; self-clean deg
__global__ void k_dinv(const float* __restrict__ x, const int* __restrict__ batch) {
    int n = blockIdx.x * blockDim.x + threadIdx.x;
    if (n >= N_NODES) return;
    float deg = g_deg[n];
    g_deg[n] = 0.0f;                             // ready for next call
    float di = rsqrtf(deg + 1.0f);
    float xd = __ldg(&x[n]) * di;
    g_nd[n] = make_float2(di, __int_as_float(__ldg(&batch[n])));
    g_xd[n] = xd;
    g_t[n]  = xd;                                // self-loop seed
    if (n == 0) { g_sum = 0.0; g_sumsq = 0.0; }
}

// K3: t[d] += xd[s]*w   (4 edges/thread)
__global__ void k_agg1(const int4* __restrict__ src4, const int4* __restrict__ dst4,
                       const float4* __restrict__ ew4) {
    int i = blockIdx.x * blockDim.x + threadIdx.x;
    if (i >= NQ) return;
    int4   s = __ldg(&src4[i]);
    int4   d = __ldg(&dst4[i]);
    float4 w = __ldg(&ew4[i]);
    float x0 = g_xd[s.x], x1 = g_xd[s.y], x2 = g_xd[s.z], x3 = g_xd[s.w];
    atomicAdd(&g_t[d.x], x0 * w.x); atomicAdd(&g_t[d.y], x1 * w.y);
    atomicAdd(&g_t[d.z], x2 * w.z); atomicAdd(&g_t[d.w], x3 * w.w);
}

// K4: mean/var of a_n = dinv[n]*t[n]
__global__ void k_reduce() {
    __shared__ float ss[8], sq[8];
    int tid = threadIdx.x, lane = tid & 31, wrp = tid >> 5;
    float a = 0.f, b = 0.f;
    for (int n = blockIdx.x * blockDim.x + tid; n < N_NODES; n += gridDim.x * blockDim.x) {
        float v = g_nd[n].x * g_t[n];
        a += v; b += v * v;
    }
#pragma unroll
    for (int o = 16; o; o >>= 1) {
        a += __shfl_down_sync(0xffffffffu, a, o);
        b += __shfl_down_sync(0xffffffffu, b, o);
    }
    if (lane == 0) { ss[wrp] = a; sq[wrp] = b; }
    __syncthreads();
    if (wrp == 0) {
        a = (lane < 8) ? ss[lane] : 0.f;
        b = (lane < 8) ? sq[lane] : 0.f;
#pragma unroll
        for (int o = 4; o; o >>= 1) {
            a += __shfl_down_sync(0xffffffffu, a, o);
            b += __shfl_down_sync(0xffffffffu, b, o);
        }
        if (lane == 0) {
            atomicAdd(&g_sum,   (double)a);
            atomicAdd(&g_sumsq, (double)b);
        }
    }
}

// K5: hhd[n] = (relu(a*S+T)@W2)*dinv ; accumulate self-loop pool term + counts
__global__ void k_hh(const float* __restrict__ W1, const float* __restrict__ gamma,
                     const float* __restrict__ beta, const float* __restrict__ W2) {
    __shared__ float sS[HIDDEN], sT[HIDDEN], sW0[HIDDEN], sW1[HIDDEN];
    int tid = threadIdx.x;
    if (tid < HIDDEN) {
        float m   = (float)(g_sum / (double)N_NODES);
        float var = (float)(g_sumsq / (double)N_NODES) - m * m;
        float w   = __ldg(&W1[tid]);
        float inv = rsqrtf(var * w * w + 1e-5f);
        float sj  = w * inv * __ldg(&gamma[tid]);
        sS[tid] = sj;
        sT[tid] = __ldg(&beta[tid]) - m * sj;
        sW0[tid] = __ldg(&W2[tid * EMB + 0]);
        sW1[tid] = __ldg(&W2[tid * EMB + 1]);
    }
    __syncthreads();
    int n = blockIdx.x * blockDim.x + tid;
    bool valid = n < N_NODES;
    int g = 0; float px = 0.f, py = 0.f, c = 0.f;
    if (valid) {
        float2 nd = g_nd[n];
        float di = nd.x;
        g = __float_as_int(nd.y);
        float a  = di * g_t[n];
        float acc0 = 0.f, acc1 = 0.f;
#pragma unroll
        for (int j = 0; j < HIDDEN; j++) {
            float h = fmaxf(fmaf(a, sS[j], sT[j]), 0.0f);
            acc0 = fmaf(h, sW0[j], acc0);
            acc1 = fmaf(h, sW1[j], acc1);
        }
        g_hhd[n] = make_float2(acc0 * di, acc1 * di);
        float d2 = di * di;                       // self-loop pool term dinv^2*hh
        px = acc0 * d2; py = acc1 * d2; c = 1.f;
    }
    // warp-aggregated pool add (batch is sorted -> warps almost always uniform)
    int g0 = __shfl_sync(0xffffffffu, g, 0);
    bool uni = __all_sync(0xffffffffu, (g == g0) || !valid);
    if (uni) {
#pragma unroll
        for (int o = 16; o; o >>= 1) {
            px += __shfl_down_sync(0xffffffffu, px, o);
            py += __shfl_down_sync(0xffffffffu, py, o);
            c  += __shfl_down_sync(0xffffffffu, c,  o);
        }
        if ((tid & 31) == 0 && c > 0.f) {
            atomicAdd(&g_pool[g0 * 2 + 0], px);
            atomicAdd(&g_pool[g0 * 2 + 1], py);
            atomicAdd(&g_cnt[g0], c);
        }
    } else if (valid) {
        atomicAdd(&g_pool[g * 2 + 0], px);
        atomicAdd(&g_pool[g * 2 + 1], py);
        atomicAdd(&g_cnt[g], 1.0f);
    }
}

// K6: edge pass C straight into graph buckets:
//     pool[batch[d]] += dinv[d]*w*hhd[s]   (per-warp smem replicas, block flush)
//     last block finalizes output and self-cleans pool state.
__global__ void k_agg2(const int4* __restrict__ src4, const int4* __restrict__ dst4,
                       const float4* __restrict__ ew4, const float* __restrict__ b2,
                       float* __restrict__ out, int nblocks) {
    __shared__ float sbuf[8][N_GRAPHS * 2];      // per-warp replicas
    int tid = threadIdx.x, lane = tid & 31, wrp = tid >> 5;
    // zero replicas
    for (int k = tid; k < 8 * N_GRAPHS * 2; k += blockDim.x)
        ((float*)sbuf)[k] = 0.0f;
    __syncthreads();

    int i = blockIdx.x * blockDim.x + tid;
    if (i < NQ) {
        int4   s = __ldg(&src4[i]);
        int4   d = __ldg(&dst4[i]);
        float4 w = __ldg(&ew4[i]);
        float2 h0 = g_hhd[s.x], h1 = g_hhd[s.y], h2 = g_hhd[s.z], h3 = g_hhd[s.w];
        float2 n0 = g_nd[d.x],  n1 = g_nd[d.y],  n2 = g_nd[d.z],  n3 = g_nd[d.w];
        float* buf = sbuf[wrp];
        float c0 = n0.x * w.x; int b0 = __float_as_int(n0.y);
        float c1 = n1.x * w.y; int b1 = __float_as_int(n1.y);
        float c2 = n2.x * w.z; int b2i = __float_as_int(n2.y);
        float c3 = n3.x * w.w; int b3 = __float_as_int(n3.y);
        atomicAdd(&buf[b0 * 2 + 0], h0.x * c0); atomicAdd(&buf[b0 * 2 + 1], h0.y * c0);
        atomicAdd(&buf[b1 * 2 + 0], h1.x * c1); atomicAdd(&buf[b1 * 2 + 1], h1.y * c1);
        atomicAdd(&buf[b2i * 2 + 0], h2.x * c2); atomicAdd(&buf[b2i * 2 + 1], h2.y * c2);
        atomicAdd(&buf[b3 * 2 + 0], h3.x * c3); atomicAdd(&buf[b3 * 2 + 1], h3.y * c3);
    }
    __syncthreads();
    // flush: reduce 8 replicas -> 128 global REDs
    if (tid < N_GRAPHS * 2) {
        float v = sbuf[0][tid] + sbuf[1][tid] + sbuf[2][tid] + sbuf[3][tid]
                + sbuf[4][tid] + sbuf[5][tid] + sbuf[6][tid] + sbuf[7][tid];
        if (v != 0.0f) atomicAdd(&g_pool[tid], v);
    }
    // last-block finalize
    __shared__ bool last;
    __threadfence();
    __syncthreads();
    if (tid == 0) last = (atomicAdd(&g_done, 1u) == (unsigned)(nblocks - 1));
    __syncthreads();
    if (last) {
        if (tid < N_GRAPHS) {
            float cc = fmaxf(g_cnt[tid], 1.0f);
            out[tid * 2 + 0] = g_pool[tid * 2 + 0] / cc + __ldg(&b2[0]);
            out[tid * 2 + 1] = g_pool[tid * 2 + 1] / cc + __ldg(&b2[1]);
            g_pool[tid * 2 + 0] = 0.0f;          // self-clean for next call
            g_pool[tid * 2 + 1] = 0.0f;
            g_cnt[tid] = 0.0f;
        }
        if (tid == 0) g_done = 0u;
    }
}

extern "C" void kernel_launch(void* const* d_in, const int* in_sizes, int n_in,
                              void* d_out, int out_size) {
    const float* x     = (const float*)d_in[0];
    const int*   ei    = (const int*)  d_in[1];   // [2, E]
    const float* ew    = (const float*)d_in[2];
    const int*   batch = (const int*)  d_in[3];
    const float* W1    = (const float*)d_in[4];
    const float* gamma = (const float*)d_in[6];
    const float* beta  = (const float*)d_in[7];
    const float* W2    = (const float*)d_in[8];
    const float* b2    = (const float*)d_in[9];
    float* out = (float*)d_out;

    const int4*   src4 = (const int4*)  ei;
    const int4*   dst4 = (const int4*) (ei + N_EDGES);
    const float4* ew4  = (const float4*) ew;

    const int BT  = 256;
    const int GN  = (N_NODES + BT - 1) / BT;
    const int GE4 = (NQ + BT - 1) / BT;          // 4 edges per thread

    k_deg   <<<GE4, BT>>>(dst4, ew4);
    k_dinv  <<<GN, BT>>>(x, batch);
    k_agg1  <<<GE4, BT>>>(src4, dst4, ew4);
    k_reduce<<<148, 256>>>();
    k_hh    <<<GN, BT>>>(W1, gamma, beta, W2);
    k_agg2  <<<GE4, BT>>>(src4, dst4, ew4, b2, out, GE4);
}

// round 6
// speedup vs baseline: 1.2332x; 1.2332x over previous
#include <cuda_runtime.h>

#define N_NODES  100000
#define N_EDGES  1600000
#define HIDDEN   64
#define EMB      2
#define N_GRAPHS 64
#define NQ       (N_EDGES / 4)       // 400000 int4-quads
#define NNQ      (N_NODES / 4)       // 25000 node-quads

// -------- scratch (device globals; zero-initialized at load, self-cleaning) ----
__device__ float    g_deg[N_NODES];      // deg accumulator (zeroed by k_dinv after read)
__device__ float    g_dinv[N_NODES];     // rsqrt(deg+1)
__device__ float    g_xd[N_NODES];       // x[n]*dinv[n]
__device__ float    g_t[N_NODES];        // layer-1 unscaled agg (seeded = xd)
__device__ float2   g_hhd[N_NODES];      // hh[n]*dinv[n]
__device__ float2   g_u[N_NODES];        // layer-2 unscaled agg (seeded = hhd)
__device__ double   g_sum, g_sumsq;
__device__ float    g_pool[N_GRAPHS * 2];  // zeroed by k_pool last block
__device__ float    g_cnt[N_GRAPHS];
__device__ unsigned g_done;

// K1: deg[d] += w   (4 edges/thread)
__global__ void k_deg(const int4* __restrict__ dst4, const float4* __restrict__ ew4) {
    int i = blockIdx.x * blockDim.x + threadIdx.x;
    if (i >= NQ) return;
    int4   d = __ldg(&dst4[i]);
    float4 w = __ldg(&ew4[i]);
    atomicAdd(&g_deg[d.x], w.x); atomicAdd(&g_deg[d.y], w.y);
    atomicAdd(&g_deg[d.z], w.z); atomicAdd(&g_deg[d.w], w.w);
}

// K2: dinv = rsqrt(deg+1); xd = x*dinv; seed t; self-clean deg; zero bn sums
__global__ void k_dinv(const float* __restrict__ x) {
    int n = blockIdx.x * blockDim.x + threadIdx.x;
    if (n >= N_NODES) return;
    float deg = g_deg[n];
    g_deg[n] = 0.0f;                     // ready for next graph replay
    float di = rsqrtf(deg + 1.0f);
    float xd = __ldg(&x[n]) * di;
    g_dinv[n] = di;
    g_xd[n]   = xd;
    g_t[n]    = xd;                      // self-loop seed
    if (n == 0) { g_sum = 0.0; g_sumsq = 0.0; }
}

// K3: t[d] += xd[s]*w   (4 edges/thread)
__global__ void k_agg1(const int4* __restrict__ src4, const int4* __restrict__ dst4,
                       const float4* __restrict__ ew4) {
    int i = blockIdx.x * blockDim.x + threadIdx.x;
    if (i >= NQ) return;
    int4   s = __ldg(&src4[i]);
    int4   d = __ldg(&dst4[i]);
    float4 w = __ldg(&ew4[i]);
    float x0 = g_xd[s.x], x1 = g_xd[s.y], x2 = g_xd[s.z], x3 = g_xd[s.w];
    atomicAdd(&g_t[d.x], x0 * w.x); atomicAdd(&g_t[d.y], x1 * w.y);
    atomicAdd(&g_t[d.z], x2 * w.z); atomicAdd(&g_t[d.w], x3 * w.w);
}

// K4: mean/var of a_n = dinv[n]*t[n]  — float4 vectorized, 1 quad/thread
__global__ void k_reduce() {
    __shared__ float ss[4], sq[4];
    int tid  = threadIdx.x, lane = tid & 31, wrp = tid >> 5;
    int i = blockIdx.x * blockDim.x + tid;
    float a = 0.f, b = 0.f;
    if (i < NNQ) {
        float4 t = __ldg(&((const float4*)g_t)[i]);
        float4 d = __ldg(&((const float4*)g_dinv)[i]);
        float v0 = d.x * t.x, v1 = d.y * t.y, v2 = d.z * t.z, v3 = d.w * t.w;
        a = v0 + v1 + v2 + v3;
        b = v0 * v0 + v1 * v1 + v2 * v2 + v3 * v3;
    }
#pragma unroll
    for (int o = 16; o; o >>= 1) {
        a += __shfl_down_sync(0xffffffffu, a, o);
        b += __shfl_down_sync(0xffffffffu, b, o);
    }
    if (lane == 0) { ss[wrp] = a; sq[wrp] = b; }
    __syncthreads();
    if (tid == 0) {
        a = ss[0] + ss[1] + ss[2] + ss[3];
        b = sq[0] + sq[1] + sq[2] + sq[3];
        atomicAdd(&g_sum,   (double)a);
        atomicAdd(&g_sumsq, (double)b);
    }
}

// K5: (bnconst fused) hhd[n] = (relu(a*S+T)@W2)*dinv ; seed u with hhd
//     (self-loop pool term flows through g_u -> k_pool; do NOT add it here)
__global__ void k_hh(const float* __restrict__ W1, const float* __restrict__ gamma,
                     const float* __restrict__ beta, const float* __restrict__ W2) {
    __shared__ float sS[HIDDEN], sT[HIDDEN], sW0[HIDDEN], sW1[HIDDEN];
    int tid = threadIdx.x;
    if (tid < HIDDEN) {
        float m   = (float)(g_sum / (double)N_NODES);
        float var = (float)(g_sumsq / (double)N_NODES) - m * m;
        float w   = __ldg(&W1[tid]);
        float inv = rsqrtf(var * w * w + 1e-5f);
        float sj  = w * inv * __ldg(&gamma[tid]);
        sS[tid] = sj;
        sT[tid] = __ldg(&beta[tid]) - m * sj;
        sW0[tid] = __ldg(&W2[tid * EMB + 0]);
        sW1[tid] = __ldg(&W2[tid * EMB + 1]);
    }
    __syncthreads();
    int n = blockIdx.x * blockDim.x + tid;
    if (n >= N_NODES) return;
    float di = g_dinv[n];
    float a  = di * g_t[n];
    float acc0 = 0.f, acc1 = 0.f;
#pragma unroll
    for (int j = 0; j < HIDDEN; j++) {
        float h = fmaxf(fmaf(a, sS[j], sT[j]), 0.0f);
        acc0 = fmaf(h, sW0[j], acc0);
        acc1 = fmaf(h, sW1[j], acc1);
    }
    float2 hhd = make_float2(acc0 * di, acc1 * di);
    g_hhd[n] = hhd;
    g_u[n]   = hhd;                      // self-loop seed for layer-2 agg
}

// K6: u[d] += hhd[s]*w   (4 edges/thread, float2 vector atomics)
__global__ void k_agg2(const int4* __restrict__ src4, const int4* __restrict__ dst4,
                       const float4* __restrict__ ew4) {
    int i = blockIdx.x * blockDim.x + threadIdx.x;
    if (i >= NQ) return;
    int4   s = __ldg(&src4[i]);
    int4   d = __ldg(&dst4[i]);
    float4 w = __ldg(&ew4[i]);
    float2 h0 = g_hhd[s.x], h1 = g_hhd[s.y], h2 = g_hhd[s.z], h3 = g_hhd[s.w];
    atomicAdd(&g_u[d.x], make_float2(h0.x * w.x, h0.y * w.x));
    atomicAdd(&g_u[d.y], make_float2(h1.x * w.y, h1.y * w.y));
    atomicAdd(&g_u[d.z], make_float2(h2.x * w.z, h2.y * w.z));
    atomicAdd(&g_u[d.w], make_float2(h3.x * w.w, h3.y * w.w));
}

// K7: pool out2[n] = dinv[n]*u[n] + counts (warp-aggregated),
//     last block finalizes output and self-cleans pool state.
__global__ void k_pool(const int* __restrict__ batch, const float* __restrict__ b2,
                       float* __restrict__ out, int nblocks) {
    int tid = threadIdx.x;
    int n = blockIdx.x * blockDim.x + tid;
    bool valid = n < N_NODES;
    int g = 0; float vx = 0.f, vy = 0.f, c = 0.f;
    if (valid) {
        g = __ldg(&batch[n]);
        float di = g_dinv[n];
        float2 u = g_u[n];
        vx = u.x * di; vy = u.y * di; c = 1.f;
    }
    // batch is sorted: warps almost always graph-uniform; lane 0 valid if any lane is
    int g0 = __shfl_sync(0xffffffffu, g, 0);
    bool uni = __all_sync(0xffffffffu, (g == g0) || !valid);
    if (uni) {
#pragma unroll
        for (int o = 16; o; o >>= 1) {
            vx += __shfl_down_sync(0xffffffffu, vx, o);
            vy += __shfl_down_sync(0xffffffffu, vy, o);
            c  += __shfl_down_sync(0xffffffffu, c,  o);
        }
        if ((tid & 31) == 0 && c > 0.f) {
            atomicAdd(&g_pool[g0 * 2 + 0], vx);
            atomicAdd(&g_pool[g0 * 2 + 1], vy);
            atomicAdd(&g_cnt[g0], c);
        }
    } else if (valid) {
        atomicAdd(&g_pool[g * 2 + 0], vx);
        atomicAdd(&g_pool[g * 2 + 1], vy);
        atomicAdd(&g_cnt[g], 1.0f);
    }
    // last-block finalize + self-clean
    __shared__ bool last;
    __threadfence();
    __syncthreads();
    if (tid == 0) last = (atomicAdd(&g_done, 1u) == (unsigned)(nblocks - 1));
    __syncthreads();
    if (last) {
        if (tid < N_GRAPHS) {
            float cc = fmaxf(g_cnt[tid], 1.0f);
            out[tid * 2 + 0] = g_pool[tid * 2 + 0] / cc + __ldg(&b2[0]);
            out[tid * 2 + 1] = g_pool[tid * 2 + 1] / cc + __ldg(&b2[1]);
            g_pool[tid * 2 + 0] = 0.0f;
            g_pool[tid * 2 + 1] = 0.0f;
            g_cnt[tid] = 0.0f;
        }
        if (tid == 0) g_done = 0u;
    }
}

extern "C" void kernel_launch(void* const* d_in, const int* in_sizes, int n_in,
                              void* d_out, int out_size) {
    const float* x     = (const float*)d_in[0];
    const int*   ei    = (const int*)  d_in[1];   // [2, E]
    const float* ew    = (const float*)d_in[2];
    const int*   batch = (const int*)  d_in[3];
    const float* W1    = (const float*)d_in[4];
    const float* gamma = (const float*)d_in[6];
    const float* beta  = (const float*)d_in[7];
    const float* W2    = (const float*)d_in[8];
    const float* b2    = (const float*)d_in[9];
    float* out = (float*)d_out;

    const int4*   src4 = (const int4*)  ei;
    const int4*   dst4 = (const int4*) (ei + N_EDGES);
    const float4* ew4  = (const float4*) ew;

    const int BT  = 256;
    const int GN  = (N_NODES + BT - 1) / BT;
    const int GE4 = (NQ + BT - 1) / BT;

    k_deg   <<<GE4, BT>>>(dst4, ew4);
    k_dinv  <<<GN, BT>>>(x);
    k_agg1  <<<GE4, BT>>>(src4, dst4, ew4);
    k_reduce<<<(NNQ + 127) / 128, 128>>>();
    k_hh    <<<GN, BT>>>(W1, gamma, beta, W2);
    k_agg2  <<<GE4, BT>>>(src4, dst4, ew4);
    k_pool  <<<GN, BT>>>(batch, b2, out, GN);
}

// round 8
// speedup vs baseline: 1.2614x; 1.0229x over previous
#include <cuda_runtime.h>

#define N_NODES  100000
#define N_EDGES  1600000
#define HIDDEN   64
#define EMB      2
#define N_GRAPHS 64
#define NQ       (N_EDGES / 4)       // 400000 int4-quads
#define NN2      (N_NODES / 2)       // 50000 node-pairs

// -------- scratch (device globals; zero-initialized at load, self-cleaning) ----
__device__ float    g_deg[N_NODES];      // deg accumulator (zeroed by k_reduce after k_dinv consumed it)
__device__ float    g_dinv[N_NODES];     // rsqrt(deg+1)
__device__ float    g_xd[N_NODES];       // x[n]*dinv[n]
__device__ float    g_t[N_NODES];        // layer-1 unscaled agg (seeded = xd)
__device__ float2   g_hhd[N_NODES];      // hh[n]*dinv[n]
__device__ float2   g_u[N_NODES];        // layer-2 unscaled agg (seeded = hhd)
__device__ double   g_sum, g_sumsq;
__device__ float    g_pool[N_GRAPHS * 2];  // zeroed by k_pool last block
__device__ float    g_cnt[N_GRAPHS];
__device__ unsigned g_done;

// K1: deg[d] += w   (4 edges/thread)
__global__ void k_deg(const int4* __restrict__ dst4, const float4* __restrict__ ew4) {
    int i = blockIdx.x * blockDim.x + threadIdx.x;
    if (i >= NQ) return;
    int4   d = __ldg(&dst4[i]);
    float4 w = __ldg(&ew4[i]);
    atomicAdd(&g_deg[d.x], w.x); atomicAdd(&g_deg[d.y], w.y);
    atomicAdd(&g_deg[d.z], w.z); atomicAdd(&g_deg[d.w], w.w);
}

// K2: dinv = rsqrt(deg+1); xd = x*dinv; seed t; zero bn sums
__global__ void k_dinv(const float* __restrict__ x) {
    int n = blockIdx.x * blockDim.x + threadIdx.x;
    if (n >= N_NODES) return;
    float di = rsqrtf(g_deg[n] + 1.0f);
    float xd = __ldg(&x[n]) * di;
    g_dinv[n] = di;
    g_xd[n]   = xd;
    g_t[n]    = xd;                      // self-loop seed
    if (n == 0) { g_sum = 0.0; g_sumsq = 0.0; }
}

// K3: t[d] += xd[s]*w   (4 edges/thread)
__global__ void k_agg1(const int4* __restrict__ src4, const int4* __restrict__ dst4,
                       const float4* __restrict__ ew4) {
    int i = blockIdx.x * blockDim.x + threadIdx.x;
    if (i >= NQ) return;
    int4   s = __ldg(&src4[i]);
    int4   d = __ldg(&dst4[i]);
    float4 w = __ldg(&ew4[i]);
    float x0 = g_xd[s.x], x1 = g_xd[s.y], x2 = g_xd[s.z], x3 = g_xd[s.w];
    atomicAdd(&g_t[d.x], x0 * w.x); atomicAdd(&g_t[d.y], x1 * w.y);
    atomicAdd(&g_t[d.z], x2 * w.z); atomicAdd(&g_t[d.w], x3 * w.w);
}

// K4: mean/var of a_n = dinv[n]*t[n] — float2/thread, 256-thread blocks.
//     Also free-rides the g_deg self-clean (idle store bandwidth here).
__global__ void k_reduce() {
    __shared__ float ss[8], sq[8];
    int tid = threadIdx.x, lane = tid & 31, wrp = tid >> 5;
    int i = blockIdx.x * blockDim.x + tid;
    float a = 0.f, b = 0.f;
    if (i < NN2) {
        float2 t = __ldg(&((const float2*)g_t)[i]);
        float2 d = __ldg(&((const float2*)g_dinv)[i]);
        float v0 = d.x * t.x, v1 = d.y * t.y;
        a = v0 + v1;
        b = v0 * v0 + v1 * v1;
        ((float2*)g_deg)[i] = make_float2(0.0f, 0.0f);   // self-clean for next call
    }
#pragma unroll
    for (int o = 16; o; o >>= 1) {
        a += __shfl_down_sync(0xffffffffu, a, o);
        b += __shfl_down_sync(0xffffffffu, b, o);
    }
    if (lane == 0) { ss[wrp] = a; sq[wrp] = b; }
    __syncthreads();
    if (tid == 0) {
        a = ss[0] + ss[1] + ss[2] + ss[3] + ss[4] + ss[5] + ss[6] + ss[7];
        b = sq[0] + sq[1] + sq[2] + sq[3] + sq[4] + sq[5] + sq[6] + sq[7];
        atomicAdd(&g_sum,   (double)a);
        atomicAdd(&g_sumsq, (double)b);
    }
}

// K5: (bnconst fused) hhd[n] = (relu(a*S+T)@W2)*dinv ; seed u with hhd
__global__ void k_hh(const float* __restrict__ W1, const float* __restrict__ gamma,
                     const float* __restrict__ beta, const float* __restrict__ W2) {
    __shared__ float sS[HIDDEN], sT[HIDDEN], sW0[HIDDEN], sW1[HIDDEN];
    int tid = threadIdx.x;
    if (tid < HIDDEN) {
        float m   = (float)(g_sum / (double)N_NODES);
        float var = (float)(g_sumsq / (double)N_NODES) - m * m;
        float w   = __ldg(&W1[tid]);
        float inv = rsqrtf(var * w * w + 1e-5f);
        float sj  = w * inv * __ldg(&gamma[tid]);
        sS[tid] = sj;
        sT[tid] = __ldg(&beta[tid]) - m * sj;
        sW0[tid] = __ldg(&W2[tid * EMB + 0]);
        sW1[tid] = __ldg(&W2[tid * EMB + 1]);
    }
    __syncthreads();
    int n = blockIdx.x * blockDim.x + tid;
    if (n >= N_NODES) return;
    float di = g_dinv[n];
    float a  = di * g_t[n];
    float acc0 = 0.f, acc1 = 0.f;
#pragma unroll
    for (int j = 0; j < HIDDEN; j++) {
        float h = fmaxf(fmaf(a, sS[j], sT[j]), 0.0f);
        acc0 = fmaf(h, sW0[j], acc0);
        acc1 = fmaf(h, sW1[j], acc1);
    }
    float2 hhd = make_float2(acc0 * di, acc1 * di);
    g_hhd[n] = hhd;
    g_u[n]   = hhd;                      // self-loop seed for layer-2 agg
}

// K6: u[d] += hhd[s]*w   (4 edges/thread, float2 vector atomics)
__global__ void k_agg2(const int4* __restrict__ src4, const int4* __restrict__ dst4,
                       const float4* __restrict__ ew4) {
    int i = blockIdx.x * blockDim.x + threadIdx.x;
    if (i >= NQ) return;
    int4   s = __ldg(&src4[i]);
    int4   d = __ldg(&dst4[i]);
    float4 w = __ldg(&ew4[i]);
    float2 h0 = g_hhd[s.x], h1 = g_hhd[s.y], h2 = g_hhd[s.z], h3 = g_hhd[s.w];
    atomicAdd(&g_u[d.x], make_float2(h0.x * w.x, h0.y * w.x));
    atomicAdd(&g_u[d.y], make_float2(h1.x * w.y, h1.y * w.y));
    atomicAdd(&g_u[d.z], make_float2(h2.x * w.z, h2.y * w.z));
    atomicAdd(&g_u[d.w], make_float2(h3.x * w.w, h3.y * w.w));
}

// K7: pool out2[n] = dinv[n]*u[n] + counts (warp-aggregated),
//     last block finalizes output and self-cleans pool state.
__global__ void k_pool(const int* __restrict__ batch, const float* __restrict__ b2,
                       float* __restrict__ out, int nblocks) {
    int tid = threadIdx.x;
    int n = blockIdx.x * blockDim.x + tid;
    bool valid = n < N_NODES;
    int g = 0; float vx = 0.f, vy = 0.f, c = 0.f;
    if (valid) {
        g = __ldg(&batch[n]);
        float di = g_dinv[n];
        float2 u = g_u[n];
        vx = u.x * di; vy = u.y * di; c = 1.f;
    }
    // batch is sorted: warps almost always graph-uniform; lane 0 valid if any lane is
    int g0 = __shfl_sync(0xffffffffu, g, 0);
    bool uni = __all_sync(0xffffffffu, (g == g0) || !valid);
    if (uni) {
#pragma unroll
        for (int o = 16; o; o >>= 1) {
            vx += __shfl_down_sync(0xffffffffu, vx, o);
            vy += __shfl_down_sync(0xffffffffu, vy, o);
            c  += __shfl_down_sync(0xffffffffu, c,  o);
        }
        if ((tid & 31) == 0 && c > 0.f) {
            atomicAdd(&g_pool[g0 * 2 + 0], vx);
            atomicAdd(&g_pool[g0 * 2 + 1], vy);
            atomicAdd(&g_cnt[g0], c);
        }
    } else if (valid) {
        atomicAdd(&g_pool[g * 2 + 0], vx);
        atomicAdd(&g_pool[g * 2 + 1], vy);
        atomicAdd(&g_cnt[g], 1.0f);
    }
    // last-block finalize + self-clean
    __shared__ bool last;
    __threadfence();
    __syncthreads();
    if (tid == 0) last = (atomicAdd(&g_done, 1u) == (unsigned)(nblocks - 1));
    __syncthreads();
    if (last) {
        if (tid < N_GRAPHS) {
            float cc = fmaxf(g_cnt[tid], 1.0f);
            out[tid * 2 + 0] = g_pool[tid * 2 + 0] / cc + __ldg(&b2[0]);
            out[tid * 2 + 1] = g_pool[tid * 2 + 1] / cc + __ldg(&b2[1]);
            g_pool[tid * 2 + 0] = 0.0f;
            g_pool[tid * 2 + 1] = 0.0f;
            g_cnt[tid] = 0.0f;
        }
        if (tid == 0) g_done = 0u;
    }
}

extern "C" void kernel_launch(void* const* d_in, const int* in_sizes, int n_in,
                              void* d_out, int out_size) {
    const float* x     = (const float*)d_in[0];
    const int*   ei    = (const int*)  d_in[1];   // [2, E]
    const float* ew    = (const float*)d_in[2];
    const int*   batch = (const int*)  d_in[3];
    const float* W1    = (const float*)d_in[4];
    const float* gamma = (const float*)d_in[6];
    const float* beta  = (const float*)d_in[7];
    const float* W2    = (const float*)d_in[8];
    const float* b2    = (const float*)d_in[9];
    float* out = (float*)d_out;

    const int4*   src4 = (const int4*)  ei;
    const int4*   dst4 = (const int4*) (ei + N_EDGES);
    const float4* ew4  = (const float4*) ew;

    const int BT  = 256;
    const int GN  = (N_NODES + BT - 1) / BT;
    const int GE4 = (NQ + BT - 1) / BT;

    k_deg   <<<GE4, BT>>>(dst4, ew4);
    k_dinv  <<<GN, BT>>>(x);
    k_agg1  <<<GE4, BT>>>(src4, dst4, ew4);
    k_reduce<<<(NN2 + 255) / 256, 256>>>();
    k_hh    <<<GN, BT>>>(W1, gamma, beta, W2);
    k_agg2  <<<GE4, BT>>>(src4, dst4, ew4);
    k_pool  <<<GN, BT>>>(batch, b2, out, GN);
}